// round 1
// baseline (speedup 1.0000x reference)
#include <cuda_runtime.h>
#include <cstdint>
#include <cstddef>

// Problem constants
#define B_ROWS 32768
#define DMODEL 1024
#define NHEADS 16
#define HDIM   64

static const int GM = B_ROWS;   // GEMM M
static const int GN = DMODEL;   // GEMM N (all GEMMs are N=1024)
static const int GK = DMODEL;   // GEMM K

// GEMM tiling
#define BM 128
#define BN 128
#define BK 16
#define SA 20   // padded shared stride (floats); 20g+tig hits all 32 banks exactly once

// Scratch: 15 activation slots of B*D floats + rounded weights.
// __device__ globals are the allocation-guard-safe scratch mechanism.
#define SLOT_ELEMS 33554432ull               // B*D
__device__ float g_pool[15ull * SLOT_ELEMS]; // ~2.01 GB
#define DD 1048576ull                        // D*D
__device__ float g_wr[10ull * DD];           // rounded weights, 40 MB
// offsets into g_wr
#define OFF_QKV_C (0ull)
#define OFF_WO_C  (3ull*DD)
#define OFF_QKV_F (4ull*DD)
#define OFF_WO_F  (7ull*DD)
#define OFF_WP_C  (8ull*DD)
#define OFF_WP_F  (9ull*DD)

__device__ __forceinline__ float round_tf32(float x) {
    unsigned r;
    asm("cvt.rna.tf32.f32 %0, %1;" : "=r"(r) : "f"(x));
    return __uint_as_float(r);
}

__device__ __forceinline__ float gelu_exact(float x) {
    return 0.5f * x * (1.0f + erff(x * 0.70710678118654752440f));
}

// ---------------------------------------------------------------------------
// Elementwise: round-to-nearest tf32 copy
// ---------------------------------------------------------------------------
__global__ void round_kernel(const float* __restrict__ src, float* __restrict__ dst, size_t n) {
    size_t i  = (size_t)blockIdx.x * blockDim.x + threadIdx.x;
    size_t st = (size_t)gridDim.x * blockDim.x;
    for (; i < n; i += st) dst[i] = round_tf32(src[i]);
}

// ---------------------------------------------------------------------------
// tf32 GEMM: C[M,N] = A[M,K] @ W[N,K]^T + bias, optional exact GELU epilogue.
// 256 threads, 8 warps in 2(M) x 4(N), warp tile 64x32, mma.m16n8k8.tf32.
// ---------------------------------------------------------------------------
template <bool GELU>
__global__ __launch_bounds__(256) void gemm_kernel(
    const float* __restrict__ A, const float* __restrict__ W,
    const float* __restrict__ bias, float* __restrict__ C)
{
    __shared__ float As[2][BM * SA];
    __shared__ float Bs[2][BN * SA];

    const int tid  = threadIdx.x;
    const int m0   = blockIdx.y * BM;
    const int n0   = blockIdx.x * BN;

    const int wid  = tid >> 5;
    const int lane = tid & 31;
    const int wm   = wid >> 2;   // 0..1  (M)
    const int wn   = wid & 3;    // 0..3  (N)
    const int g    = lane >> 2;  // 0..7
    const int tig  = lane & 3;   // 0..3

    float acc[4][4][4];
#pragma unroll
    for (int i = 0; i < 4; ++i)
#pragma unroll
        for (int j = 0; j < 4; ++j)
#pragma unroll
            for (int k = 0; k < 4; ++k) acc[i][j][k] = 0.f;

    auto load_tile = [&](int kb, int bf) {
        const size_t kbase = (size_t)kb * BK;
#pragma unroll
        for (int i = 0; i < 2; ++i) {
            int f   = tid + i * 256;      // 0..511 (512 float4 per tile)
            int row = f >> 2;             // 0..127
            int c4  = (f & 3) << 2;       // 0,4,8,12
            const float* ga = A + (size_t)(m0 + row) * GK + kbase + c4;
            uint32_t sa = (uint32_t)__cvta_generic_to_shared(&As[bf][row * SA + c4]);
            asm volatile("cp.async.ca.shared.global [%0], [%1], 16;\n" :: "r"(sa), "l"(ga));
            const float* gb = W + (size_t)(n0 + row) * GK + kbase + c4;
            uint32_t sb = (uint32_t)__cvta_generic_to_shared(&Bs[bf][row * SA + c4]);
            asm volatile("cp.async.ca.shared.global [%0], [%1], 16;\n" :: "r"(sb), "l"(gb));
        }
    };

    load_tile(0, 0);
    asm volatile("cp.async.commit_group;\n");

    const int KT = GK / BK;  // 64
    int bf = 0;
    for (int kb = 0; kb < KT; ++kb) {
        asm volatile("cp.async.wait_group 0;\n");
        __syncthreads();
        if (kb + 1 < KT) {
            load_tile(kb + 1, bf ^ 1);
            asm volatile("cp.async.commit_group;\n");
        }
#pragma unroll
        for (int ks = 0; ks < 2; ++ks) {
            const int k0 = ks * 8;
            uint32_t af[4][4], bfr[4][2];
#pragma unroll
            for (int mt = 0; mt < 4; ++mt) {
                int rb = wm * 64 + mt * 16;
                af[mt][0] = __float_as_uint(As[bf][(rb + g    ) * SA + k0 + tig    ]);
                af[mt][1] = __float_as_uint(As[bf][(rb + g + 8) * SA + k0 + tig    ]);
                af[mt][2] = __float_as_uint(As[bf][(rb + g    ) * SA + k0 + tig + 4]);
                af[mt][3] = __float_as_uint(As[bf][(rb + g + 8) * SA + k0 + tig + 4]);
            }
#pragma unroll
            for (int nt = 0; nt < 4; ++nt) {
                int cb = wn * 32 + nt * 8;
                bfr[nt][0] = __float_as_uint(Bs[bf][(cb + g) * SA + k0 + tig    ]);
                bfr[nt][1] = __float_as_uint(Bs[bf][(cb + g) * SA + k0 + tig + 4]);
            }
#pragma unroll
            for (int mt = 0; mt < 4; ++mt)
#pragma unroll
                for (int nt = 0; nt < 4; ++nt) {
                    asm volatile(
                        "mma.sync.aligned.m16n8k8.row.col.f32.tf32.tf32.f32 "
                        "{%0,%1,%2,%3}, {%4,%5,%6,%7}, {%8,%9}, {%0,%1,%2,%3};\n"
                        : "+f"(acc[mt][nt][0]), "+f"(acc[mt][nt][1]),
                          "+f"(acc[mt][nt][2]), "+f"(acc[mt][nt][3])
                        : "r"(af[mt][0]), "r"(af[mt][1]), "r"(af[mt][2]), "r"(af[mt][3]),
                          "r"(bfr[nt][0]), "r"(bfr[nt][1]));
                }
        }
        __syncthreads();
        bf ^= 1;
    }

    // epilogue
#pragma unroll
    for (int mt = 0; mt < 4; ++mt) {
#pragma unroll
        for (int nt = 0; nt < 4; ++nt) {
            int m = m0 + wm * 64 + mt * 16 + g;
            int n = n0 + wn * 32 + nt * 8 + tig * 2;
            float bv0 = bias ? bias[n]     : 0.f;
            float bv1 = bias ? bias[n + 1] : 0.f;
            float v0 = acc[mt][nt][0] + bv0;
            float v1 = acc[mt][nt][1] + bv1;
            float v2 = acc[mt][nt][2] + bv0;
            float v3 = acc[mt][nt][3] + bv1;
            if (GELU) {
                v0 = gelu_exact(v0); v1 = gelu_exact(v1);
                v2 = gelu_exact(v2); v3 = gelu_exact(v3);
            }
            *(float2*)&C[(size_t)m       * GN + n] = make_float2(v0, v1);
            *(float2*)&C[(size_t)(m + 8) * GN + n] = make_float2(v2, v3);
        }
    }
}

// ---------------------------------------------------------------------------
// Attention: one warp per (b, h). seq_q = 1, seq_k = 2.
// For conf branch: q = (1+S[b]) * Qraw + bq  (Qraw = Z_T @ Wq^T, no bias).
// Output rounded to tf32 (feeds next GEMM's A operand).
// ---------------------------------------------------------------------------
__global__ __launch_bounds__(256) void attn_kernel(
    const float* __restrict__ Q,  const float* __restrict__ K0, const float* __restrict__ K1,
    const float* __restrict__ V0, const float* __restrict__ V1,
    const float* __restrict__ Sconf, const float* __restrict__ qbias,
    float* __restrict__ AO)
{
    int gw   = (int)((blockIdx.x * blockDim.x + threadIdx.x) >> 5);
    int lane = threadIdx.x & 31;
    int b = gw >> 4;
    int h = gw & 15;
    size_t base = (size_t)b * DMODEL + h * HDIM;

    float q0 = Q[base + lane], q1 = Q[base + lane + 32];
    if (Sconf) {
        float s = 1.f + Sconf[b];
        q0 = fmaf(s, q0, qbias[h * HDIM + lane]);
        q1 = fmaf(s, q1, qbias[h * HDIM + lane + 32]);
    }
    float s0 = q0 * K0[base + lane] + q1 * K0[base + lane + 32];
    float s1 = q0 * K1[base + lane] + q1 * K1[base + lane + 32];
#pragma unroll
    for (int o = 16; o; o >>= 1) {
        s0 += __shfl_xor_sync(0xffffffffu, s0, o);
        s1 += __shfl_xor_sync(0xffffffffu, s1, o);
    }
    s0 *= 0.125f;  // 1/sqrt(64)
    s1 *= 0.125f;
    float mx = fmaxf(s0, s1);
    float e0 = expf(s0 - mx), e1 = expf(s1 - mx);
    float inv = 1.f / (e0 + e1);
    float a0 = e0 * inv, a1 = e1 * inv;
    float o0 = a0 * V0[base + lane]      + a1 * V1[base + lane];
    float o1 = a0 * V0[base + lane + 32] + a1 * V1[base + lane + 32];
    AO[base + lane]      = round_tf32(o0);
    AO[base + lane + 32] = round_tf32(o1);
}

// ---------------------------------------------------------------------------
// LayerNorm: one warp per row of 1024. Output rounded to tf32.
// ---------------------------------------------------------------------------
__global__ __launch_bounds__(256) void ln_kernel(
    const float* __restrict__ X,
    const float* __restrict__ gamma, const float* __restrict__ beta,
    float* __restrict__ Y)
{
    int row  = (int)((blockIdx.x * blockDim.x + threadIdx.x) >> 5);
    int lane = threadIdx.x & 31;
    const float* x = X + (size_t)row * DMODEL;
    float v[32];
    float s = 0.f, sq = 0.f;
#pragma unroll
    for (int i = 0; i < 32; ++i) {
        v[i] = x[lane + 32 * i];
        s += v[i];
        sq += v[i] * v[i];
    }
#pragma unroll
    for (int o = 16; o; o >>= 1) {
        s  += __shfl_xor_sync(0xffffffffu, s, o);
        sq += __shfl_xor_sync(0xffffffffu, sq, o);
    }
    float mean = s * (1.f / 1024.f);
    float var  = sq * (1.f / 1024.f) - mean * mean;
    float r = rsqrtf(var + 1e-5f);
    float* y = Y + (size_t)row * DMODEL;
#pragma unroll
    for (int i = 0; i < 32; ++i) {
        int d = lane + 32 * i;
        y[d] = round_tf32((v[i] - mean) * r * gamma[d] + beta[d]);
    }
}

// ---------------------------------------------------------------------------
// Launch
// ---------------------------------------------------------------------------
extern "C" void kernel_launch(void* const* d_in, const int* in_sizes, int n_in,
                              void* d_out, int out_size)
{
    const float* Z_T       = (const float*)d_in[0];
    const float* Z_V       = (const float*)d_in[1];
    const float* Z_A       = (const float*)d_in[2];
    const float* S         = (const float*)d_in[3];
    const float* Wqkv_cons = (const float*)d_in[4];
    const float* bqkv_cons = (const float*)d_in[5];
    const float* Wo_cons   = (const float*)d_in[6];
    const float* bo_cons   = (const float*)d_in[7];
    const float* Wqkv_conf = (const float*)d_in[8];
    const float* bqkv_conf = (const float*)d_in[9];
    const float* Wo_conf   = (const float*)d_in[10];
    const float* bo_conf   = (const float*)d_in[11];
    const float* Wp_cons   = (const float*)d_in[12];
    const float* bp_cons   = (const float*)d_in[13];
    const float* Wp_conf   = (const float*)d_in[14];
    const float* bp_conf   = (const float*)d_in[15];
    const float* gamma     = (const float*)d_in[16];
    const float* beta      = (const float*)d_in[17];
    float* out = (float*)d_out;

    void* pp = nullptr; cudaGetSymbolAddress(&pp, g_pool);
    void* wp = nullptr; cudaGetSymbolAddress(&wp, g_wr);
    float* pool = (float*)pp;
    float* wr   = (float*)wp;

    auto slot = [&](int i) { return pool + (size_t)i * SLOT_ELEMS; };

    // --- Round inputs & weights to tf32 (round-to-nearest; avoids truncation bias) ---
    round_kernel<<<2048, 256>>>(Z_T, slot(0), SLOT_ELEMS);
    round_kernel<<<2048, 256>>>(Z_V, slot(1), SLOT_ELEMS);
    round_kernel<<<2048, 256>>>(Z_A, slot(2), SLOT_ELEMS);
    round_kernel<<<512, 256>>>(Wqkv_cons, wr + OFF_QKV_C, 3 * DD);
    round_kernel<<<512, 256>>>(Wo_cons,   wr + OFF_WO_C,  DD);
    round_kernel<<<512, 256>>>(Wqkv_conf, wr + OFF_QKV_F, 3 * DD);
    round_kernel<<<512, 256>>>(Wo_conf,   wr + OFF_WO_F,  DD);
    round_kernel<<<512, 256>>>(Wp_cons,   wr + OFF_WP_C,  DD);
    round_kernel<<<512, 256>>>(Wp_conf,   wr + OFF_WP_F,  DD);

    dim3 grid(GN / BN, GM / BM);  // (8, 256)

    // --- QKV projections, cons branch ---
    gemm_kernel<false><<<grid, 256>>>(slot(0), wr + OFF_QKV_C,          bqkv_cons,              slot(3));  // Qc
    gemm_kernel<false><<<grid, 256>>>(slot(1), wr + OFF_QKV_C + DD,     bqkv_cons + DMODEL,     slot(4));  // K0c
    gemm_kernel<false><<<grid, 256>>>(slot(2), wr + OFF_QKV_C + DD,     bqkv_cons + DMODEL,     slot(5));  // K1c
    gemm_kernel<false><<<grid, 256>>>(slot(1), wr + OFF_QKV_C + 2 * DD, bqkv_cons + 2 * DMODEL, slot(6));  // V0c
    gemm_kernel<false><<<grid, 256>>>(slot(2), wr + OFF_QKV_C + 2 * DD, bqkv_cons + 2 * DMODEL, slot(7));  // V1c
    // --- QKV projections, conf branch (Q without bias: fused later with (1+S) scale) ---
    gemm_kernel<false><<<grid, 256>>>(slot(0), wr + OFF_QKV_F,          nullptr,                slot(8));  // Qf raw
    gemm_kernel<false><<<grid, 256>>>(slot(1), wr + OFF_QKV_F + DD,     bqkv_conf + DMODEL,     slot(9));  // K0f
    gemm_kernel<false><<<grid, 256>>>(slot(2), wr + OFF_QKV_F + DD,     bqkv_conf + DMODEL,     slot(10)); // K1f
    gemm_kernel<false><<<grid, 256>>>(slot(1), wr + OFF_QKV_F + 2 * DD, bqkv_conf + 2 * DMODEL, slot(11)); // V0f
    gemm_kernel<false><<<grid, 256>>>(slot(2), wr + OFF_QKV_F + 2 * DD, bqkv_conf + 2 * DMODEL, slot(12)); // V1f

    // --- Attention (B*H warps) ---
    attn_kernel<<<65536, 256>>>(slot(3), slot(4), slot(5), slot(6), slot(7),
                                nullptr, nullptr, slot(13));                   // AOc
    attn_kernel<<<65536, 256>>>(slot(8), slot(9), slot(10), slot(11), slot(12),
                                S, bqkv_conf, slot(14));                       // AOf

    // --- Output projections ---
    gemm_kernel<false><<<grid, 256>>>(slot(13), wr + OFF_WO_C, bo_cons, slot(3));  // Cc
    gemm_kernel<false><<<grid, 256>>>(slot(14), wr + OFF_WO_F, bo_conf, slot(4));  // Cf

    // --- LayerNorm ---
    ln_kernel<<<4096, 256>>>(slot(3), gamma, beta, slot(5));  // LNc
    ln_kernel<<<4096, 256>>>(slot(4), gamma, beta, slot(6));  // LNf

    // --- Final projection + exact GELU, straight into d_out ---
    gemm_kernel<true><<<grid, 256>>>(slot(5), wr + OFF_WP_C, bp_cons, out);
    gemm_kernel<true><<<grid, 256>>>(slot(6), wr + OFF_WP_F, bp_conf, out + (size_t)B_ROWS * DMODEL);
}

// round 3
// speedup vs baseline: 1.2654x; 1.2654x over previous
#include <cuda_runtime.h>
#include <cstdint>
#include <cstddef>

// ---------------------------------------------------------------------------
// Problem constants
// ---------------------------------------------------------------------------
#define BROWS  32768
#define DMODEL 1024
#define NHEADS 16
#define HDIM   64

static const int GM = BROWS;
static const int GN = DMODEL;

// Scratch (__device__ globals = allocation-guard-safe)
#define SLOT_ELEMS 33554432ull                 // B*D
__device__ float g_pool[15ull * SLOT_ELEMS];   // ~2.01 GB
#define DD 1048576ull                          // D*D
__device__ float g_wr[10ull * DD];             // packed weights

// ---------------------------------------------------------------------------
// Helpers
// ---------------------------------------------------------------------------
__device__ __forceinline__ float round_tf32(float x) {
    unsigned r; asm("cvt.rna.tf32.f32 %0, %1;" : "=r"(r) : "f"(x));
    return __uint_as_float(r);
}
__device__ __forceinline__ float gelu_exact(float x) {
    return 0.5f * x * (1.0f + erff(x * 0.70710678118654752440f));
}

// Packed-A index: tile(128 rows) x kchunk(32 cols) chunks of 4096 floats.
// Within chunk: wm(2)*2048 + ks(4)*512 + mt(4)*128 + lane(32)*4 + w(4)
// row = mtile*128 + wm*64 + mt*16 + (w&1)*8 + g ;  g = lane>>2
// col = kb*32 + ks*8 + ((w>>1)&1)*4 + tig       ;  tig = lane&3
__device__ __forceinline__ size_t packA_idx(uint32_t row, uint32_t col) {
    uint32_t mtile = row >> 7, r = row & 127;
    uint32_t wm = r >> 6, mt = (r >> 4) & 3, wb = (r >> 3) & 1, g = r & 7;
    uint32_t kb = col >> 5, ks = (col >> 3) & 3, w2 = (col >> 2) & 1, tig = col & 3;
    return ((size_t)(mtile * 32 + kb) << 12) + (wm << 11) + (ks << 9) + (mt << 7)
         + ((g * 4 + tig) << 2) + (w2 * 2 + wb);
}

// ---------------------------------------------------------------------------
// Pack kernels: round to tf32 (rna) + fragment-major reorder
// ---------------------------------------------------------------------------
__global__ void pack_a(const float* __restrict__ src, float* __restrict__ dst, size_t n) {
    size_t i  = (size_t)blockIdx.x * blockDim.x + threadIdx.x;
    size_t st = (size_t)gridDim.x * blockDim.x;
    for (; i < n; i += st) {
        uint32_t chunk = (uint32_t)(i >> 12), within = (uint32_t)(i & 4095);
        uint32_t mtile = chunk >> 5, kb = chunk & 31;
        uint32_t wm = within >> 11, ks = (within >> 9) & 3, mt = (within >> 7) & 3;
        uint32_t lane = (within >> 2) & 31, w = within & 3;
        uint32_t g = lane >> 2, tig = lane & 3;
        uint32_t row = mtile * 128 + wm * 64 + mt * 16 + (w & 1) * 8 + g;
        uint32_t col = kb * 32 + ks * 8 + ((w >> 1) & 1) * 4 + tig;
        dst[i] = round_tf32(src[(size_t)row * 1024 + col]);
    }
}
// Packed-W: ntile(128 rows) x kchunk(32) chunks of 4096 floats.
// Within chunk: wn(4)*1024 + ks(4)*256 + pair(2)*128 + lane*4 + w
// n = ntile*128 + wn*32 + pair*16 + ((w>>1)&1)*8 + g
// k = kb*32 + ks*8 + (w&1)*4 + tig
__global__ void pack_w(const float* __restrict__ src, float* __restrict__ dst, size_t n) {
    size_t i  = (size_t)blockIdx.x * blockDim.x + threadIdx.x;
    size_t st = (size_t)gridDim.x * blockDim.x;
    for (; i < n; i += st) {
        uint32_t chunk = (uint32_t)(i >> 12), within = (uint32_t)(i & 4095);
        uint32_t ntile = chunk >> 5, kb = chunk & 31;
        uint32_t wn = within >> 10, ks = (within >> 8) & 3, pair = (within >> 7) & 1;
        uint32_t lane = (within >> 2) & 31, w = within & 3;
        uint32_t g = lane >> 2, tig = lane & 3;
        uint32_t nn = ntile * 128 + wn * 32 + pair * 16 + ((w >> 1) & 1) * 8 + g;
        uint32_t kk = kb * 32 + ks * 8 + (w & 1) * 4 + tig;
        dst[i] = round_tf32(src[(size_t)nn * 1024 + kk]);
    }
}

// ---------------------------------------------------------------------------
// tf32 GEMM, fragment-packed operands. C = A @ W^T + bias (optional GELU).
// Tile 128x128x32, 8 warps (2x4), warp tile 64x32, 5-stage cp.async pipeline.
// ---------------------------------------------------------------------------
#define NST 5
#define STAGE_A 16384
#define STAGE_B 16384
#define SMEM_GEMM (NST * (STAGE_A + STAGE_B))   // 163840

template <bool GELU>
__global__ __launch_bounds__(256) void gemm_tc(
    const float* __restrict__ Ap, const float* __restrict__ Wp,
    const float* __restrict__ bias, float* __restrict__ C)
{
    extern __shared__ float smem[];
    float* As = smem;                       // NST * 4096 floats
    float* Bs = smem + NST * 4096;          // NST * 4096 floats

    const int tid  = threadIdx.x;
    const int ntb  = blockIdx.x;            // 0..7
    const int mtb  = blockIdx.y;            // 0..255
    const int wid  = tid >> 5;
    const int lane = tid & 31;
    const int wm   = wid >> 2;              // 0..1
    const int wn   = wid & 3;               // 0..3
    const int g    = lane >> 2;
    const int tig  = lane & 3;

    const float* Abase = Ap + ((size_t)mtb * 32 << 12);
    const float* Bbase = Wp + ((size_t)ntb * 32 << 12);

    auto load_stage = [&](int s, int c) {
        const float* ga = Abase + ((size_t)c << 12) + tid * 4;
        const float* gb = Bbase + ((size_t)c << 12) + tid * 4;
        float* sa = As + s * 4096 + tid * 4;
        float* sb = Bs + s * 4096 + tid * 4;
#pragma unroll
        for (int j = 0; j < 4; ++j) {
            uint32_t da = (uint32_t)__cvta_generic_to_shared(sa + j * 1024);
            asm volatile("cp.async.cg.shared.global [%0], [%1], 16;\n" :: "r"(da), "l"(ga + j * 1024));
            uint32_t db = (uint32_t)__cvta_generic_to_shared(sb + j * 1024);
            asm volatile("cp.async.cg.shared.global [%0], [%1], 16;\n" :: "r"(db), "l"(gb + j * 1024));
        }
        asm volatile("cp.async.commit_group;\n");
    };

    float acc[4][4][4];
#pragma unroll
    for (int i = 0; i < 4; ++i)
#pragma unroll
        for (int j = 0; j < 4; ++j)
#pragma unroll
            for (int k = 0; k < 4; ++k) acc[i][j][k] = 0.f;

#pragma unroll
    for (int s = 0; s < NST - 1; ++s) load_stage(s, s);

    for (int c = 0; c < 32; ++c) {
        asm volatile("cp.async.wait_group %0;\n" :: "n"(NST - 2));
        __syncthreads();
        if (c + NST - 1 < 32) load_stage((c + NST - 1) % NST, c + NST - 1);

        const float4* A4 = (const float4*)(As + (c % NST) * 4096) + wm * 512 + lane;
        const float4* B4 = (const float4*)(Bs + (c % NST) * 4096) + wn * 256 + lane;
#pragma unroll
        for (int ks = 0; ks < 4; ++ks) {
            float4 av[4], bv[2];
#pragma unroll
            for (int mt = 0; mt < 4; ++mt) av[mt] = A4[ks * 128 + mt * 32];
#pragma unroll
            for (int p = 0; p < 2; ++p)  bv[p] = B4[ks * 64 + p * 32];
#pragma unroll
            for (int mt = 0; mt < 4; ++mt) {
                const uint32_t a0 = __float_as_uint(av[mt].x), a1 = __float_as_uint(av[mt].y);
                const uint32_t a2 = __float_as_uint(av[mt].z), a3 = __float_as_uint(av[mt].w);
#pragma unroll
                for (int p = 0; p < 2; ++p) {
                    const uint32_t b00 = __float_as_uint(bv[p].x), b01 = __float_as_uint(bv[p].y);
                    const uint32_t b10 = __float_as_uint(bv[p].z), b11 = __float_as_uint(bv[p].w);
                    asm volatile(
                        "mma.sync.aligned.m16n8k8.row.col.f32.tf32.tf32.f32 "
                        "{%0,%1,%2,%3}, {%4,%5,%6,%7}, {%8,%9}, {%0,%1,%2,%3};\n"
                        : "+f"(acc[mt][2*p][0]), "+f"(acc[mt][2*p][1]),
                          "+f"(acc[mt][2*p][2]), "+f"(acc[mt][2*p][3])
                        : "r"(a0), "r"(a1), "r"(a2), "r"(a3), "r"(b00), "r"(b01));
                    asm volatile(
                        "mma.sync.aligned.m16n8k8.row.col.f32.tf32.tf32.f32 "
                        "{%0,%1,%2,%3}, {%4,%5,%6,%7}, {%8,%9}, {%0,%1,%2,%3};\n"
                        : "+f"(acc[mt][2*p+1][0]), "+f"(acc[mt][2*p+1][1]),
                          "+f"(acc[mt][2*p+1][2]), "+f"(acc[mt][2*p+1][3])
                        : "r"(a0), "r"(a1), "r"(a2), "r"(a3), "r"(b10), "r"(b11));
                }
            }
        }
    }

    // epilogue: thread (g,tig) holds c[g][2tig], c[g][2tig+1], c[g+8][...]
#pragma unroll
    for (int mt = 0; mt < 4; ++mt) {
#pragma unroll
        for (int nt = 0; nt < 4; ++nt) {
            int m = mtb * 128 + wm * 64 + mt * 16 + g;
            int n = ntb * 128 + wn * 32 + nt * 8 + tig * 2;
            float bv0 = bias ? bias[n]     : 0.f;
            float bv1 = bias ? bias[n + 1] : 0.f;
            float v0 = acc[mt][nt][0] + bv0;
            float v1 = acc[mt][nt][1] + bv1;
            float v2 = acc[mt][nt][2] + bv0;
            float v3 = acc[mt][nt][3] + bv1;
            if (GELU) {
                v0 = gelu_exact(v0); v1 = gelu_exact(v1);
                v2 = gelu_exact(v2); v3 = gelu_exact(v3);
            }
            *(float2*)&C[(size_t)m       * GN + n] = make_float2(v0, v1);
            *(float2*)&C[(size_t)(m + 8) * GN + n] = make_float2(v2, v3);
        }
    }
}

// ---------------------------------------------------------------------------
// Attention: one warp per (b, h). seq_q=1, seq_k=2. Writes packed-A tf32.
// ---------------------------------------------------------------------------
__global__ __launch_bounds__(256) void attn_kernel(
    const float* __restrict__ Q,  const float* __restrict__ K0, const float* __restrict__ K1,
    const float* __restrict__ V0, const float* __restrict__ V1,
    const float* __restrict__ Sconf, const float* __restrict__ qbias,
    float* __restrict__ AO)
{
    int gw   = (int)((blockIdx.x * blockDim.x + threadIdx.x) >> 5);
    int lane = threadIdx.x & 31;
    int b = gw >> 4;
    int h = gw & 15;
    size_t base = (size_t)b * DMODEL + h * HDIM;

    float q0 = Q[base + lane], q1 = Q[base + lane + 32];
    if (Sconf) {
        float s = 1.f + Sconf[b];
        q0 = fmaf(s, q0, qbias[h * HDIM + lane]);
        q1 = fmaf(s, q1, qbias[h * HDIM + lane + 32]);
    }
    float s0 = q0 * K0[base + lane] + q1 * K0[base + lane + 32];
    float s1 = q0 * K1[base + lane] + q1 * K1[base + lane + 32];
#pragma unroll
    for (int o = 16; o; o >>= 1) {
        s0 += __shfl_xor_sync(0xffffffffu, s0, o);
        s1 += __shfl_xor_sync(0xffffffffu, s1, o);
    }
    s0 *= 0.125f;
    s1 *= 0.125f;
    float mx = fmaxf(s0, s1);
    float e0 = expf(s0 - mx), e1 = expf(s1 - mx);
    float inv = 1.f / (e0 + e1);
    float a0 = e0 * inv, a1 = e1 * inv;
    float o0 = a0 * V0[base + lane]      + a1 * V1[base + lane];
    float o1 = a0 * V0[base + lane + 32] + a1 * V1[base + lane + 32];

    AO[packA_idx((uint32_t)b, (uint32_t)(h * HDIM + lane))]      = round_tf32(o0);
    AO[packA_idx((uint32_t)b, (uint32_t)(h * HDIM + lane + 32))] = round_tf32(o1);
}

// ---------------------------------------------------------------------------
// LayerNorm: one warp per row. Writes packed-A tf32.
// ---------------------------------------------------------------------------
__global__ __launch_bounds__(256) void ln_kernel(
    const float* __restrict__ X,
    const float* __restrict__ gamma, const float* __restrict__ beta,
    float* __restrict__ Y)
{
    int row  = (int)((blockIdx.x * blockDim.x + threadIdx.x) >> 5);
    int lane = threadIdx.x & 31;
    const float* x = X + (size_t)row * DMODEL;
    float v[32];
    float s = 0.f, sq = 0.f;
#pragma unroll
    for (int i = 0; i < 32; ++i) {
        v[i] = x[lane + 32 * i];
        s += v[i];
        sq += v[i] * v[i];
    }
#pragma unroll
    for (int o = 16; o; o >>= 1) {
        s  += __shfl_xor_sync(0xffffffffu, s, o);
        sq += __shfl_xor_sync(0xffffffffu, sq, o);
    }
    float mean = s * (1.f / 1024.f);
    float var  = sq * (1.f / 1024.f) - mean * mean;
    float rr = rsqrtf(var + 1e-5f);
#pragma unroll
    for (int i = 0; i < 32; ++i) {
        int d = lane + 32 * i;
        float y = (v[i] - mean) * rr * gamma[d] + beta[d];
        Y[packA_idx((uint32_t)row, (uint32_t)d)] = round_tf32(y);
    }
}

// ---------------------------------------------------------------------------
// Launch
// ---------------------------------------------------------------------------
extern "C" void kernel_launch(void* const* d_in, const int* in_sizes, int n_in,
                              void* d_out, int out_size)
{
    const float* Z_T       = (const float*)d_in[0];
    const float* Z_V       = (const float*)d_in[1];
    const float* Z_A       = (const float*)d_in[2];
    const float* S         = (const float*)d_in[3];
    const float* Wqkv_cons = (const float*)d_in[4];
    const float* bqkv_cons = (const float*)d_in[5];
    const float* Wo_cons   = (const float*)d_in[6];
    const float* bo_cons   = (const float*)d_in[7];
    const float* Wqkv_conf = (const float*)d_in[8];
    const float* bqkv_conf = (const float*)d_in[9];
    const float* Wo_conf   = (const float*)d_in[10];
    const float* bo_conf   = (const float*)d_in[11];
    const float* Wp_cons   = (const float*)d_in[12];
    const float* bp_cons   = (const float*)d_in[13];
    const float* Wp_conf   = (const float*)d_in[14];
    const float* bp_conf   = (const float*)d_in[15];
    const float* gamma     = (const float*)d_in[16];
    const float* beta      = (const float*)d_in[17];
    float* out = (float*)d_out;

    void* pp = nullptr; cudaGetSymbolAddress(&pp, g_pool);
    void* wp = nullptr; cudaGetSymbolAddress(&wp, g_wr);
    float* pool = (float*)pp;
    float* wr   = (float*)wp;
    auto slot = [&](int i) { return pool + (size_t)i * SLOT_ELEMS; };

    cudaFuncSetAttribute(gemm_tc<false>, cudaFuncAttributeMaxDynamicSharedMemorySize, SMEM_GEMM);
    cudaFuncSetAttribute(gemm_tc<true>,  cudaFuncAttributeMaxDynamicSharedMemorySize, SMEM_GEMM);

    // --- Pack inputs & weights ---
    pack_a<<<2048, 256>>>(Z_T, slot(0), SLOT_ELEMS);
    pack_a<<<2048, 256>>>(Z_V, slot(1), SLOT_ELEMS);
    pack_a<<<2048, 256>>>(Z_A, slot(2), SLOT_ELEMS);
    pack_w<<<512, 256>>>(Wqkv_cons, wr + 0ull * DD, 3 * DD);
    pack_w<<<512, 256>>>(Wo_cons,   wr + 3ull * DD, DD);
    pack_w<<<512, 256>>>(Wqkv_conf, wr + 4ull * DD, 3 * DD);
    pack_w<<<512, 256>>>(Wo_conf,   wr + 7ull * DD, DD);
    pack_w<<<512, 256>>>(Wp_cons,   wr + 8ull * DD, DD);
    pack_w<<<512, 256>>>(Wp_conf,   wr + 9ull * DD, DD);

    dim3 grid(8, 256);

    // --- QKV projections (Qf raw: bias fused into attn with (1+S) scale) ---
    gemm_tc<false><<<grid, 256, SMEM_GEMM>>>(slot(0), wr + 0ull * DD, bqkv_cons,        slot(3));  // Qc
    gemm_tc<false><<<grid, 256, SMEM_GEMM>>>(slot(1), wr + 1ull * DD, bqkv_cons + 1024, slot(4));  // K0c
    gemm_tc<false><<<grid, 256, SMEM_GEMM>>>(slot(2), wr + 1ull * DD, bqkv_cons + 1024, slot(5));  // K1c
    gemm_tc<false><<<grid, 256, SMEM_GEMM>>>(slot(1), wr + 2ull * DD, bqkv_cons + 2048, slot(6));  // V0c
    gemm_tc<false><<<grid, 256, SMEM_GEMM>>>(slot(2), wr + 2ull * DD, bqkv_cons + 2048, slot(7));  // V1c
    gemm_tc<false><<<grid, 256, SMEM_GEMM>>>(slot(0), wr + 4ull * DD, (const float*)0,  slot(8));  // Qf raw
    gemm_tc<false><<<grid, 256, SMEM_GEMM>>>(slot(1), wr + 5ull * DD, bqkv_conf + 1024, slot(9));  // K0f
    gemm_tc<false><<<grid, 256, SMEM_GEMM>>>(slot(2), wr + 5ull * DD, bqkv_conf + 1024, slot(10)); // K1f
    gemm_tc<false><<<grid, 256, SMEM_GEMM>>>(slot(1), wr + 6ull * DD, bqkv_conf + 2048, slot(11)); // V0f
    gemm_tc<false><<<grid, 256, SMEM_GEMM>>>(slot(2), wr + 6ull * DD, bqkv_conf + 2048, slot(12)); // V1f

    // --- Attention (writes packed-A) ---
    attn_kernel<<<65536, 256>>>(slot(3), slot(4), slot(5), slot(6), slot(7),
                                (const float*)0, (const float*)0, slot(13));
    attn_kernel<<<65536, 256>>>(slot(8), slot(9), slot(10), slot(11), slot(12),
                                S, bqkv_conf, slot(14));

    // --- Output projections (row-major out for LN) ---
    gemm_tc<false><<<grid, 256, SMEM_GEMM>>>(slot(13), wr + 3ull * DD, bo_cons, slot(3));
    gemm_tc<false><<<grid, 256, SMEM_GEMM>>>(slot(14), wr + 7ull * DD, bo_conf, slot(4));

    // --- LayerNorm (writes packed-A) ---
    ln_kernel<<<4096, 256>>>(slot(3), gamma, beta, slot(5));
    ln_kernel<<<4096, 256>>>(slot(4), gamma, beta, slot(6));

    // --- Final projection + exact GELU into d_out ---
    gemm_tc<true><<<grid, 256, SMEM_GEMM>>>(slot(5), wr + 8ull * DD, bp_cons, out);
    gemm_tc<true><<<grid, 256, SMEM_GEMM>>>(slot(6), wr + 9ull * DD, bp_conf, out + (size_t)BROWS * DMODEL);
}

// round 4
// speedup vs baseline: 2.4237x; 1.9153x over previous
#include <cuda_runtime.h>
#include <cuda_fp16.h>
#include <cstdint>
#include <cstddef>

// ---------------------------------------------------------------------------
// Problem constants
// ---------------------------------------------------------------------------
#define BROWS  32768
#define DMODEL 1024
#define NHEADS 16
#define HDIM   64

static const int GN = DMODEL;

// Scratch (__device__ globals = allocation-guard-safe)
// fp32 slots F0..F6 (7 x 128MB) then fp16 packed region P0..P6 (7 x 64MB)
#define SLOT_ELEMS 33554432ull                 // B*D
__device__ float g_pool[11ull * SLOT_ELEMS];   // 7 fp32 + 3.5 (fp16 packed)
#define DD 1048576ull                          // D*D
__device__ float g_wr[5ull * DD + 16];         // 10*DD halves packed weights

// ---------------------------------------------------------------------------
// Helpers
// ---------------------------------------------------------------------------
__device__ __forceinline__ float gelu_exact(float x) {
    return 0.5f * x * (1.0f + erff(x * 0.70710678118654752440f));
}

// Packed-A (fp16) index for row-major activation [row, col] -> fragment-major.
// chunk(4096 halves) = (mtile, kb); unit(8 halves) = wm,ks,mt,lane; reg/lo within.
__device__ __forceinline__ size_t packA_idx_h(uint32_t row, uint32_t col) {
    uint32_t mtile = row >> 7, r = row & 127;
    uint32_t wm = r >> 6, mt = (r >> 4) & 3, b8 = (r >> 3) & 1, g = r & 7;
    uint32_t kb = col >> 5, c5 = col & 31;
    uint32_t ks = c5 >> 4, c4 = c5 & 15;
    uint32_t hi8 = c4 >> 3, rem = c4 & 7, tig = rem >> 1, lo = rem & 1;
    uint32_t reg = hi8 * 2 + b8;
    uint32_t u = ((wm * 2 + ks) * 4 + mt) * 32 + g * 4 + tig;
    return (((size_t)(mtile * 32 + kb)) << 12) + u * 8 + reg * 2 + lo;
}

// ---------------------------------------------------------------------------
// Pack kernels: fp32 -> fp16 (RN) + fragment-major reorder
// ---------------------------------------------------------------------------
__global__ void pack_a(const float* __restrict__ src, __half* __restrict__ dst, size_t n) {
    size_t i  = (size_t)blockIdx.x * blockDim.x + threadIdx.x;
    size_t st = (size_t)gridDim.x * blockDim.x;
    for (; i < n; i += st) {
        uint32_t chunk = (uint32_t)(i >> 12), w = (uint32_t)(i & 4095);
        uint32_t u = w >> 3, h = w & 7;
        uint32_t lane = u & 31, mt = (u >> 5) & 3, ks = (u >> 7) & 1, wm = (u >> 8) & 1;
        uint32_t mtile = chunk >> 5, kb = chunk & 31;
        uint32_t g = lane >> 2, tig = lane & 3;
        uint32_t reg = h >> 1, lo = h & 1;
        uint32_t row = mtile * 128 + wm * 64 + mt * 16 + (reg & 1) * 8 + g;
        uint32_t col = kb * 32 + ks * 16 + (reg >> 1) * 8 + tig * 2 + lo;
        dst[i] = __float2half_rn(src[(size_t)row * 1024 + col]);
    }
}
// Packed-W: chunk = (ntile of 128 N-rows, kb); unit = wn,ks,p,lane.
// 16B unit = {b0,b1 of nt=2p, b0,b1 of nt=2p+1}
__global__ void pack_w(const float* __restrict__ src, __half* __restrict__ dst, size_t n) {
    size_t i  = (size_t)blockIdx.x * blockDim.x + threadIdx.x;
    size_t st = (size_t)gridDim.x * blockDim.x;
    for (; i < n; i += st) {
        uint32_t chunk = (uint32_t)(i >> 12), w = (uint32_t)(i & 4095);
        uint32_t u = w >> 3, h = w & 7;
        uint32_t lane = u & 31, p = (u >> 5) & 1, ks = (u >> 6) & 1, wn = (u >> 7) & 3;
        uint32_t ntile = chunk >> 5, kb = chunk & 31;
        uint32_t g = lane >> 2, tig = lane & 3;
        uint32_t reg = h >> 1;
        uint32_t nt = p * 2 + (reg >> 1), breg = reg & 1;
        uint32_t nn = ntile * 128 + wn * 32 + nt * 8 + g;
        uint32_t kk = kb * 32 + ks * 16 + breg * 8 + tig * 2 + (h & 1);
        dst[i] = __float2half_rn(src[(size_t)nn * 1024 + kk]);
    }
}

// ---------------------------------------------------------------------------
// fp16 GEMM (fp32 accum): C = A @ W^T + bias (optional GELU).
// Tile 128x128x32, 8 warps (2x4), warp tile 64x32, mma.m16n8k16, 5 stages.
// Stage = 512 uint4 A + 512 uint4 B = 16KB.
// ---------------------------------------------------------------------------
#define NST 5
#define SMEM_GEMM (NST * 1024 * 16)   // 81920

template <bool GELU>
__global__ __launch_bounds__(256) void gemm_fp16(
    const uint4* __restrict__ Ap, const uint4* __restrict__ Wp,
    const float* __restrict__ bias, float* __restrict__ C)
{
    extern __shared__ uint4 sm4[];
    uint4* As = sm4;
    uint4* Bs = sm4 + NST * 512;

    const int tid  = threadIdx.x;
    const int ntb  = blockIdx.x;
    const int mtb  = blockIdx.y;
    const int wid  = tid >> 5;
    const int lane = tid & 31;
    const int wm   = wid >> 2;
    const int wn   = wid & 3;
    const int g    = lane >> 2;
    const int tig  = lane & 3;

    const uint4* Abase = Ap + ((size_t)mtb * 32) * 512;
    const uint4* Bbase = Wp + ((size_t)ntb * 32) * 512;

    auto load_stage = [&](int s, int c) {
        const uint4* ga = Abase + (size_t)c * 512 + tid;
        const uint4* gb = Bbase + (size_t)c * 512 + tid;
        uint4* sa = As + s * 512 + tid;
        uint4* sb = Bs + s * 512 + tid;
#pragma unroll
        for (int j = 0; j < 2; ++j) {
            uint32_t da = (uint32_t)__cvta_generic_to_shared(sa + j * 256);
            asm volatile("cp.async.cg.shared.global [%0], [%1], 16;\n" :: "r"(da), "l"(ga + j * 256));
            uint32_t db = (uint32_t)__cvta_generic_to_shared(sb + j * 256);
            asm volatile("cp.async.cg.shared.global [%0], [%1], 16;\n" :: "r"(db), "l"(gb + j * 256));
        }
        asm volatile("cp.async.commit_group;\n");
    };

    float acc[4][4][4];
#pragma unroll
    for (int i = 0; i < 4; ++i)
#pragma unroll
        for (int j = 0; j < 4; ++j)
#pragma unroll
            for (int k = 0; k < 4; ++k) acc[i][j][k] = 0.f;

#pragma unroll
    for (int s = 0; s < NST - 1; ++s) load_stage(s, s);

    for (int c = 0; c < 32; ++c) {
        asm volatile("cp.async.wait_group %0;\n" :: "n"(NST - 2));
        __syncthreads();
        if (c + NST - 1 < 32) load_stage((c + NST - 1) % NST, c + NST - 1);

        const uint4* A4 = As + (c % NST) * 512 + wm * 256 + lane;
        const uint4* B4 = Bs + (c % NST) * 512 + wn * 128 + lane;
#pragma unroll
        for (int ks = 0; ks < 2; ++ks) {
            uint4 av[4], bv[2];
#pragma unroll
            for (int mt = 0; mt < 4; ++mt) av[mt] = A4[ks * 128 + mt * 32];
#pragma unroll
            for (int p = 0; p < 2; ++p)  bv[p] = B4[ks * 64 + p * 32];
#pragma unroll
            for (int mt = 0; mt < 4; ++mt) {
#pragma unroll
                for (int p = 0; p < 2; ++p) {
                    asm volatile(
                        "mma.sync.aligned.m16n8k16.row.col.f32.f16.f16.f32 "
                        "{%0,%1,%2,%3}, {%4,%5,%6,%7}, {%8,%9}, {%0,%1,%2,%3};\n"
                        : "+f"(acc[mt][2*p][0]), "+f"(acc[mt][2*p][1]),
                          "+f"(acc[mt][2*p][2]), "+f"(acc[mt][2*p][3])
                        : "r"(av[mt].x), "r"(av[mt].y), "r"(av[mt].z), "r"(av[mt].w),
                          "r"(bv[p].x), "r"(bv[p].y));
                    asm volatile(
                        "mma.sync.aligned.m16n8k16.row.col.f32.f16.f16.f32 "
                        "{%0,%1,%2,%3}, {%4,%5,%6,%7}, {%8,%9}, {%0,%1,%2,%3};\n"
                        : "+f"(acc[mt][2*p+1][0]), "+f"(acc[mt][2*p+1][1]),
                          "+f"(acc[mt][2*p+1][2]), "+f"(acc[mt][2*p+1][3])
                        : "r"(av[mt].x), "r"(av[mt].y), "r"(av[mt].z), "r"(av[mt].w),
                          "r"(bv[p].z), "r"(bv[p].w));
                }
            }
        }
    }

    // epilogue
#pragma unroll
    for (int mt = 0; mt < 4; ++mt) {
#pragma unroll
        for (int nt = 0; nt < 4; ++nt) {
            int m = mtb * 128 + wm * 64 + mt * 16 + g;
            int n = ntb * 128 + wn * 32 + nt * 8 + tig * 2;
            float bv0 = bias ? bias[n]     : 0.f;
            float bv1 = bias ? bias[n + 1] : 0.f;
            float v0 = acc[mt][nt][0] + bv0;
            float v1 = acc[mt][nt][1] + bv1;
            float v2 = acc[mt][nt][2] + bv0;
            float v3 = acc[mt][nt][3] + bv1;
            if (GELU) {
                v0 = gelu_exact(v0); v1 = gelu_exact(v1);
                v2 = gelu_exact(v2); v3 = gelu_exact(v3);
            }
            *(float2*)&C[(size_t)m       * GN + n] = make_float2(v0, v1);
            *(float2*)&C[(size_t)(m + 8) * GN + n] = make_float2(v2, v3);
        }
    }
}

// ---------------------------------------------------------------------------
// Attention: one warp per (b, h). seq_q=1, seq_k=2. Writes packed-A fp16.
// ---------------------------------------------------------------------------
__global__ __launch_bounds__(256) void attn_kernel(
    const float* __restrict__ Q,  const float* __restrict__ K0, const float* __restrict__ K1,
    const float* __restrict__ V0, const float* __restrict__ V1,
    const float* __restrict__ Sconf, const float* __restrict__ qbias,
    __half* __restrict__ AO)
{
    int gw   = (int)((blockIdx.x * blockDim.x + threadIdx.x) >> 5);
    int lane = threadIdx.x & 31;
    int b = gw >> 4;
    int h = gw & 15;
    size_t base = (size_t)b * DMODEL + h * HDIM;

    float q0 = Q[base + lane], q1 = Q[base + lane + 32];
    if (Sconf) {
        float s = 1.f + Sconf[b];
        q0 = fmaf(s, q0, qbias[h * HDIM + lane]);
        q1 = fmaf(s, q1, qbias[h * HDIM + lane + 32]);
    }
    float s0 = q0 * K0[base + lane] + q1 * K0[base + lane + 32];
    float s1 = q0 * K1[base + lane] + q1 * K1[base + lane + 32];
#pragma unroll
    for (int o = 16; o; o >>= 1) {
        s0 += __shfl_xor_sync(0xffffffffu, s0, o);
        s1 += __shfl_xor_sync(0xffffffffu, s1, o);
    }
    s0 *= 0.125f;
    s1 *= 0.125f;
    float mx = fmaxf(s0, s1);
    float e0 = expf(s0 - mx), e1 = expf(s1 - mx);
    float inv = 1.f / (e0 + e1);
    float a0 = e0 * inv, a1 = e1 * inv;
    float o0 = a0 * V0[base + lane]      + a1 * V1[base + lane];
    float o1 = a0 * V0[base + lane + 32] + a1 * V1[base + lane + 32];

    AO[packA_idx_h((uint32_t)b, (uint32_t)(h * HDIM + lane))]      = __float2half_rn(o0);
    AO[packA_idx_h((uint32_t)b, (uint32_t)(h * HDIM + lane + 32))] = __float2half_rn(o1);
}

// ---------------------------------------------------------------------------
// LayerNorm: one warp per row. Writes packed-A fp16.
// ---------------------------------------------------------------------------
__global__ __launch_bounds__(256) void ln_kernel(
    const float* __restrict__ X,
    const float* __restrict__ gamma, const float* __restrict__ beta,
    __half* __restrict__ Y)
{
    int row  = (int)((blockIdx.x * blockDim.x + threadIdx.x) >> 5);
    int lane = threadIdx.x & 31;
    const float* x = X + (size_t)row * DMODEL;
    float v[32];
    float s = 0.f, sq = 0.f;
#pragma unroll
    for (int i = 0; i < 32; ++i) {
        v[i] = x[lane + 32 * i];
        s += v[i];
        sq += v[i] * v[i];
    }
#pragma unroll
    for (int o = 16; o; o >>= 1) {
        s  += __shfl_xor_sync(0xffffffffu, s, o);
        sq += __shfl_xor_sync(0xffffffffu, sq, o);
    }
    float mean = s * (1.f / 1024.f);
    float var  = sq * (1.f / 1024.f) - mean * mean;
    float rr = rsqrtf(var + 1e-5f);
#pragma unroll
    for (int i = 0; i < 32; ++i) {
        int d = lane + 32 * i;
        float y = (v[i] - mean) * rr * gamma[d] + beta[d];
        Y[packA_idx_h((uint32_t)row, (uint32_t)d)] = __float2half_rn(y);
    }
}

// ---------------------------------------------------------------------------
// Launch
// ---------------------------------------------------------------------------
extern "C" void kernel_launch(void* const* d_in, const int* in_sizes, int n_in,
                              void* d_out, int out_size)
{
    const float* Z_T       = (const float*)d_in[0];
    const float* Z_V       = (const float*)d_in[1];
    const float* Z_A       = (const float*)d_in[2];
    const float* S         = (const float*)d_in[3];
    const float* Wqkv_cons = (const float*)d_in[4];
    const float* bqkv_cons = (const float*)d_in[5];
    const float* Wo_cons   = (const float*)d_in[6];
    const float* bo_cons   = (const float*)d_in[7];
    const float* Wqkv_conf = (const float*)d_in[8];
    const float* bqkv_conf = (const float*)d_in[9];
    const float* Wo_conf   = (const float*)d_in[10];
    const float* bo_conf   = (const float*)d_in[11];
    const float* Wp_cons   = (const float*)d_in[12];
    const float* bp_cons   = (const float*)d_in[13];
    const float* Wp_conf   = (const float*)d_in[14];
    const float* bp_conf   = (const float*)d_in[15];
    const float* gamma     = (const float*)d_in[16];
    const float* beta      = (const float*)d_in[17];
    float* out = (float*)d_out;

    void* pp = nullptr; cudaGetSymbolAddress(&pp, g_pool);
    void* wp = nullptr; cudaGetSymbolAddress(&wp, g_wr);
    float*  pool  = (float*)pp;
    __half* wh    = (__half*)wp;
    __half* hbase = (__half*)(pool + 7ull * SLOT_ELEMS);

    auto F = [&](int i) { return pool + (size_t)i * SLOT_ELEMS; };
    auto P = [&](int j) { return hbase + (size_t)j * SLOT_ELEMS; };
    auto W = [&](int i) { return (const uint4*)(wh + (size_t)i * DD); };
    auto P4 = [&](int j) { return (const uint4*)P(j); };

    cudaFuncSetAttribute(gemm_fp16<false>, cudaFuncAttributeMaxDynamicSharedMemorySize, SMEM_GEMM);
    cudaFuncSetAttribute(gemm_fp16<true>,  cudaFuncAttributeMaxDynamicSharedMemorySize, SMEM_GEMM);

    // --- Pack (fp32 -> fp16 fragment-major) ---
    pack_a<<<2048, 256>>>(Z_T, P(0), SLOT_ELEMS);
    pack_a<<<2048, 256>>>(Z_V, P(1), SLOT_ELEMS);
    pack_a<<<2048, 256>>>(Z_A, P(2), SLOT_ELEMS);   // P(1),P(2) contiguous -> merged M=65536
    pack_w<<<512, 256>>>(Wqkv_cons, wh + 0ull * DD, 3 * DD);  // Wq_c,Wk_c,Wv_c
    pack_w<<<512, 256>>>(Wo_cons,   wh + 3ull * DD, DD);
    pack_w<<<512, 256>>>(Wqkv_conf, wh + 4ull * DD, 3 * DD);  // Wq_f,Wk_f,Wv_f
    pack_w<<<512, 256>>>(Wo_conf,   wh + 7ull * DD, DD);
    pack_w<<<512, 256>>>(Wp_cons,   wh + 8ull * DD, DD);
    pack_w<<<512, 256>>>(Wp_conf,   wh + 9ull * DD, DD);

    dim3 g1(8, 256), g2(8, 512);

    // --- cons branch QKV (K,V merged over both kv inputs) ---
    gemm_fp16<false><<<g1, 256, SMEM_GEMM>>>(P4(0), W(0), bqkv_cons,        F(0));  // Qc
    gemm_fp16<false><<<g2, 256, SMEM_GEMM>>>(P4(1), W(1), bqkv_cons + 1024, F(1));  // K0c|K1c
    gemm_fp16<false><<<g2, 256, SMEM_GEMM>>>(P4(1), W(2), bqkv_cons + 2048, F(3));  // V0c|V1c
    attn_kernel<<<65536, 256>>>(F(0), F(1), F(2), F(3), F(4),
                                (const float*)0, (const float*)0, P(3));            // AOc

    // --- conf branch QKV (Q raw: bias fused in attn with (1+S) scale) ---
    gemm_fp16<false><<<g1, 256, SMEM_GEMM>>>(P4(0), W(4), (const float*)0,  F(0));  // Qf raw
    gemm_fp16<false><<<g2, 256, SMEM_GEMM>>>(P4(1), W(5), bqkv_conf + 1024, F(1));  // K0f|K1f
    gemm_fp16<false><<<g2, 256, SMEM_GEMM>>>(P4(1), W(6), bqkv_conf + 2048, F(3));  // V0f|V1f
    attn_kernel<<<65536, 256>>>(F(0), F(1), F(2), F(3), F(4),
                                S, bqkv_conf, P(4));                                // AOf

    // --- Output projections ---
    gemm_fp16<false><<<g1, 256, SMEM_GEMM>>>(P4(3), W(3), bo_cons, F(5));           // Cc
    gemm_fp16<false><<<g1, 256, SMEM_GEMM>>>(P4(4), W(7), bo_conf, F(6));           // Cf

    // --- LayerNorm ---
    ln_kernel<<<4096, 256>>>(F(5), gamma, beta, P(5));
    ln_kernel<<<4096, 256>>>(F(6), gamma, beta, P(6));

    // --- Final projection + exact GELU into d_out ---
    gemm_fp16<true><<<g1, 256, SMEM_GEMM>>>(P4(5), W(8), bp_cons, out);
    gemm_fp16<true><<<g1, 256, SMEM_GEMM>>>(P4(6), W(9), bp_conf, out + (size_t)BROWS * DMODEL);
}